// round 1
// baseline (speedup 1.0000x reference)
#include <cuda_runtime.h>

#define BB 64
#define TT 100
#define DD 32
#define LL 64
#define KK 16
#define HH 50
#define NT 512

// ---------------- global scratch (no allocation allowed) ----------------
__device__ float g_w[BB * TT * KK];
__device__ float g_muf[BB * TT * LL];
__device__ float g_mup[BB * TT * LL];
__device__ float g_Sigf[(size_t)BB * TT * LL * LL];
__device__ float g_Sigp[(size_t)BB * TT * LL * LL];

// ---------------- helpers ----------------
__device__ __forceinline__ void fma8(float acc[8], float a, const float* p) {
    float4 v0 = *(const float4*)p;
    float4 v1 = *(const float4*)(p + 4);
    acc[0] = fmaf(a, v0.x, acc[0]);
    acc[1] = fmaf(a, v0.y, acc[1]);
    acc[2] = fmaf(a, v0.z, acc[2]);
    acc[3] = fmaf(a, v0.w, acc[3]);
    acc[4] = fmaf(a, v1.x, acc[4]);
    acc[5] = fmaf(a, v1.y, acc[5]);
    acc[6] = fmaf(a, v1.z, acc[6]);
    acc[7] = fmaf(a, v1.w, acc[7]);
}

__device__ __forceinline__ void store8(float* p, const float acc[8]) {
    *(float4*)p       = make_float4(acc[0], acc[1], acc[2], acc[3]);
    *(float4*)(p + 4) = make_float4(acc[4], acc[5], acc[6], acc[7]);
}

// ---------------- kernel 1: mixing weights w = softmax(MLP(joint)) ----------------
__global__ void w_kernel(const float* __restrict__ obs, const float* __restrict__ start,
                         const float* __restrict__ W1, const float* __restrict__ b1,
                         const float* __restrict__ W2, const float* __restrict__ b2) {
    __shared__ float sj[DD];
    __shared__ float sh[HH];
    __shared__ float se[KK];
    int bt = blockIdx.x;
    int b = bt / TT, t = bt % TT;
    int tid = threadIdx.x;
    if (tid < DD) sj[tid] = (t == 0) ? start[tid] : obs[((size_t)b * TT + t - 1) * DD + tid];
    __syncthreads();
    if (tid < HH) {
        float a = b1[tid];
        for (int d = 0; d < DD; d++) a = fmaf(sj[d], W1[d * HH + tid], a);
        sh[tid] = fmaxf(a, 0.f);
    }
    __syncthreads();
    if (tid < KK) {
        float a = b2[tid];
        for (int j = 0; j < HH; j++) a = fmaf(sh[j], W2[j * KK + tid], a);
        se[tid] = a;
    }
    __syncthreads();
    if (tid == 0) {
        float m = se[0];
        for (int k = 1; k < KK; k++) m = fmaxf(m, se[k]);
        float ex[KK];
        float ssum = 0.f;
        for (int k = 0; k < KK; k++) { ex[k] = expf(se[k] - m); ssum += ex[k]; }
        float inv = 1.f / ssum;
        for (int k = 0; k < KK; k++) g_w[bt * KK + k] = ex[k] * inv;
    }
}

// ---------------- kernel 2: A_t / C_t mixing: out[bt, :] = sum_k w[bt,k] * M[k, :] ----------------
__global__ void mix_kernel(const float* __restrict__ M, float* __restrict__ out, int ncols) {
    __shared__ float sM[KK * 512];
    __shared__ float sw[32 * KK];
    int tid = threadIdx.x;
    int ij0 = blockIdx.x * 512;
    int bt0 = blockIdx.y * 32;
    for (int idx = tid * 4; idx < KK * 512; idx += 256 * 4) {
        int k = idx / 512, c = idx % 512;
        *(float4*)&sM[idx] = *(const float4*)&M[(size_t)k * ncols + ij0 + c];
    }
    sw[tid]       = g_w[bt0 * KK + tid];
    sw[tid + 256] = g_w[bt0 * KK + tid + 256];
    __syncthreads();

    int btl = (tid >> 5) * 4;       // 8 groups * 4 = 32 bt rows
    int jl  = (tid & 31) * 16;      // 32 * 16 = 512 cols
    float acc[4][16];
#pragma unroll
    for (int u = 0; u < 4; u++)
#pragma unroll
        for (int v = 0; v < 16; v++) acc[u][v] = 0.f;

    for (int k = 0; k < KK; k++) {
        float w0 = sw[(btl + 0) * KK + k];
        float w1 = sw[(btl + 1) * KK + k];
        float w2 = sw[(btl + 2) * KK + k];
        float w3 = sw[(btl + 3) * KK + k];
        float m[16];
#pragma unroll
        for (int v = 0; v < 16; v += 4) *(float4*)&m[v] = *(float4*)&sM[k * 512 + jl + v];
#pragma unroll
        for (int v = 0; v < 16; v++) {
            acc[0][v] = fmaf(w0, m[v], acc[0][v]);
            acc[1][v] = fmaf(w1, m[v], acc[1][v]);
            acc[2][v] = fmaf(w2, m[v], acc[2][v]);
            acc[3][v] = fmaf(w3, m[v], acc[3][v]);
        }
    }
#pragma unroll
    for (int u = 0; u < 4; u++) {
        float* dst = &out[(size_t)(bt0 + btl + u) * ncols + ij0 + jl];
#pragma unroll
        for (int v = 0; v < 16; v += 4)
            *(float4*)&dst[v] = make_float4(acc[u][v], acc[u][v + 1], acc[u][v + 2], acc[u][v + 3]);
    }
}

// ---------------- forward Kalman filter: one CTA per batch ----------------
struct FwdS {
    float Sig[LL * LL];    // carry: predicted covariance (stride 64)
    float AtT[LL * 68];    // A_t transposed (stride 68)
    float Ct[DD * LL];
    float CS[DD * LL];     // C@Sig, becomes Kg^T after GJ
    float S[DD * 33];      // innovation cov (stride 33)
    float ImT[LL * 68];    // (I - Kg C)^T (stride 68)
    float T1[LL * LL];     // Im@Sig, reused as At@Sigz
    float Sigz[LL * LL];
    float mu[LL];
    float muz[LL];
    float r[DD];
    float y[DD];
    float F[DD];
};

extern __shared__ char smem_raw[];

__global__ __launch_bounds__(NT, 1) void fwd_kernel(const float* __restrict__ obs,
                                                    const float* __restrict__ outA,
                                                    const float* __restrict__ outC) {
    FwdS& s = *(FwdS*)smem_raw;
    int tid = threadIdx.x;
    int b = blockIdx.x;
    for (int o = tid; o < LL * LL; o += NT) s.Sig[o] = ((o >> 6) == (o & 63)) ? 20.f : 0.f;
    if (tid < LL) s.mu[tid] = 0.f;
    __syncthreads();

    int ti = tid >> 3;              // 0..63
    int tj0 = (tid & 7) * 8;        // 0..56
    int sd = tid >> 4;              // 0..31
    int sj0 = (tid & 15) * 4;       // 0..60

    for (int t = 0; t < TT; t++) {
        const float* Ag = outA + (size_t)(b * TT + t) * (LL * LL);
        const float* Cg = outC + (size_t)(b * TT + t) * (DD * LL);
        for (int o = tid * 4; o < LL * LL; o += NT * 4) {
            float4 v = *(const float4*)(Ag + o);
            int i = o >> 6, j = o & 63;
            s.AtT[(j + 0) * 68 + i] = v.x;
            s.AtT[(j + 1) * 68 + i] = v.y;
            s.AtT[(j + 2) * 68 + i] = v.z;
            s.AtT[(j + 3) * 68 + i] = v.w;
        }
        for (int o = tid * 4; o < DD * LL; o += NT * 4)
            *(float4*)&s.Ct[o] = *(const float4*)&Cg[o];
        if (tid < DD) s.y[tid] = obs[((size_t)b * TT + t) * DD + tid];
        __syncthreads();

        // CS = C @ Sig (32x64), r = y - C mu
        {
            float4 acc = {0.f, 0.f, 0.f, 0.f};
            for (int k = 0; k < LL; k++) {
                float a = s.Ct[sd * LL + k];
                float4 sv = *(float4*)&s.Sig[k * LL + sj0];
                acc.x = fmaf(a, sv.x, acc.x);
                acc.y = fmaf(a, sv.y, acc.y);
                acc.z = fmaf(a, sv.z, acc.z);
                acc.w = fmaf(a, sv.w, acc.w);
            }
            *(float4*)&s.CS[sd * LL + sj0] = acc;
            if (tid < DD) {
                float a = s.y[tid];
                for (int l = 0; l < LL; l++) a = fmaf(-s.Ct[tid * LL + l], s.mu[l], a);
                s.r[tid] = a;
            }
        }
        __syncthreads();

        // S = CS @ C^T + 0.3 I (32x32, stride 33)
        {
            int e0 = (tid & 15) * 2;
            float a0 = (sd == e0) ? 0.3f : 0.f;
            float a1 = (sd == e0 + 1) ? 0.3f : 0.f;
            for (int k = 0; k < LL; k++) {
                float c = s.CS[sd * LL + k];
                a0 = fmaf(c, s.Ct[e0 * LL + k], a0);
                a1 = fmaf(c, s.Ct[(e0 + 1) * LL + k], a1);
            }
            s.S[sd * 33 + e0] = a0;
            s.S[sd * 33 + e0 + 1] = a1;
        }
        __syncthreads();

        // Gauss-Jordan: [S | CS] -> CS becomes Kg^T = S^{-1} C Sig (S is SPD, no pivoting)
        for (int p = 0; p < DD; p++) {
            if (tid < DD) s.F[tid] = s.S[tid * 33 + p];
            __syncthreads();
            if (tid < 96) {
                float inv = 1.f / s.F[p];
                if (tid < 32) s.S[p * 33 + tid] *= inv;
                else s.CS[p * LL + tid - 32] *= inv;
            }
            __syncthreads();
            for (int idx = tid; idx < 32 * 96; idx += NT) {
                int rr = idx / 96, c = idx % 96;
                if (rr != p) {
                    float f = s.F[rr];
                    if (c < 32) s.S[rr * 33 + c] = fmaf(-f, s.S[p * 33 + c], s.S[rr * 33 + c]);
                    else {
                        int cc = c - 32;
                        s.CS[rr * LL + cc] = fmaf(-f, s.CS[p * LL + cc], s.CS[rr * LL + cc]);
                    }
                }
            }
            __syncthreads();
        }

        // mu_z = mu + Kg r ; Im^T (stride 68): Im = I - Kg C
        if (tid < LL) {
            float a = s.mu[tid];
            for (int m = 0; m < DD; m++) a = fmaf(s.CS[m * LL + tid], s.r[m], a);
            s.muz[tid] = a;
        }
        {
            float acc[8];
#pragma unroll
            for (int u = 0; u < 8; u++) acc[u] = (ti == tj0 + u) ? 1.f : 0.f;
            for (int m = 0; m < DD; m++) fma8(acc, -s.CS[m * LL + ti], &s.Ct[m * LL + tj0]);
#pragma unroll
            for (int u = 0; u < 8; u++) s.ImT[(tj0 + u) * 68 + ti] = acc[u];
        }
        __syncthreads();

        // T1 = Im @ Sig
        {
            float acc[8] = {0.f, 0.f, 0.f, 0.f, 0.f, 0.f, 0.f, 0.f};
            for (int k = 0; k < LL; k++) fma8(acc, s.ImT[k * 68 + ti], &s.Sig[k * LL + tj0]);
            store8(&s.T1[ti * LL + tj0], acc);
        }
        __syncthreads();

        // Sigz = T1 @ Im^T + 0.3 Kg Kg^T
        {
            float acc[8] = {0.f, 0.f, 0.f, 0.f, 0.f, 0.f, 0.f, 0.f};
            for (int k = 0; k < LL; k++) fma8(acc, s.T1[ti * LL + k], &s.ImT[k * 68 + tj0]);
            for (int m = 0; m < DD; m++) fma8(acc, 0.3f * s.CS[m * LL + ti], &s.CS[m * LL + tj0]);
            store8(&s.Sigz[ti * LL + tj0], acc);
        }
        __syncthreads();

        // store mu_f/Sig_f (posterior) and mu_p/Sig_p (carry at entry); T2 = At @ Sigz into T1
        {
            size_t gb = (size_t)t * BB + b;
            if (tid < LL) {
                g_muf[gb * LL + tid] = s.muz[tid];
                g_mup[gb * LL + tid] = s.mu[tid];
            }
            for (int o = tid * 4; o < LL * LL; o += NT * 4) {
                *(float4*)&g_Sigf[gb * 4096 + o] = *(float4*)&s.Sigz[o];
                *(float4*)&g_Sigp[gb * 4096 + o] = *(float4*)&s.Sig[o];
            }
            float acc[8] = {0.f, 0.f, 0.f, 0.f, 0.f, 0.f, 0.f, 0.f};
            for (int l = 0; l < LL; l++) fma8(acc, s.AtT[l * 68 + ti], &s.Sigz[l * LL + tj0]);
            __syncthreads();
            store8(&s.T1[ti * LL + tj0], acc);
        }
        __syncthreads();

        // Sig_new = T2 @ At^T + 0.8 I ; mu_new = At mu_z
        {
            float acc[8] = {0.f, 0.f, 0.f, 0.f, 0.f, 0.f, 0.f, 0.f};
            for (int k = 0; k < LL; k++) fma8(acc, s.T1[ti * LL + k], &s.AtT[k * 68 + tj0]);
#pragma unroll
            for (int u = 0; u < 8; u++)
                if (ti == tj0 + u) acc[u] += 0.8f;
            store8(&s.Sig[ti * LL + tj0], acc);
            if (tid < LL) {
                float a = 0.f;
                for (int k = 0; k < LL; k++) a = fmaf(s.AtT[k * 68 + tid], s.muz[k], a);
                s.mu[tid] = a;
            }
        }
        __syncthreads();
    }
}

// ---------------- backward RTS smoother: one CTA per batch ----------------
struct BwdS {
    float Sigs[LL * LL];   // carry: smoothed cov at t+1
    float Sf[LL * LL];
    float Sp[LL * 65];     // Sig_p[t+1], stride 65 for GJ
    float M[LL * LL];      // A@Sf -> becomes J^T after GJ
    float E[LL * LL];      // Sigs - Sp
    float T1[LL * LL];
    float AtT[LL * 68];
    float mus[LL];
    float mf[LL];
    float mp1[LL];
    float dvec[LL];
    float F[LL];
};

__global__ __launch_bounds__(NT, 1) void bwd_kernel(const float* __restrict__ outA,
                                                    float* __restrict__ outMu,
                                                    float* __restrict__ outSig) {
    BwdS& s = *(BwdS*)smem_raw;
    int tid = threadIdx.x;
    int b = blockIdx.x;
    int ti = tid >> 3;
    int tj0 = (tid & 7) * 8;

    {
        size_t gb = (size_t)(TT - 1) * BB + b;
        for (int o = tid * 4; o < LL * LL; o += NT * 4) {
            float4 v = *(const float4*)&g_Sigf[gb * 4096 + o];
            *(float4*)&s.Sigs[o] = v;
            *(float4*)&outSig[gb * 4096 + o] = v;
        }
        if (tid < LL) {
            float v = g_muf[gb * LL + tid];
            s.mus[tid] = v;
            outMu[gb * LL + tid] = v;
        }
    }
    __syncthreads();

    for (int t = TT - 2; t >= 0; t--) {
        size_t gf = (size_t)t * BB + b;
        size_t gp = (size_t)(t + 1) * BB + b;
        const float* Ag = outA + ((size_t)b * TT + (t + 1)) * (LL * LL);
        for (int o = tid * 4; o < LL * LL; o += NT * 4) {
            float4 v = *(const float4*)(Ag + o);
            int i = o >> 6, j = o & 63;
            s.AtT[(j + 0) * 68 + i] = v.x;
            s.AtT[(j + 1) * 68 + i] = v.y;
            s.AtT[(j + 2) * 68 + i] = v.z;
            s.AtT[(j + 3) * 68 + i] = v.w;
            *(float4*)&s.Sf[o] = *(const float4*)&g_Sigf[gf * 4096 + o];
        }
        for (int o = tid; o < LL * LL; o += NT)
            s.Sp[(o >> 6) * 65 + (o & 63)] = g_Sigp[gp * 4096 + o];
        if (tid < LL) {
            s.mf[tid] = g_muf[gf * LL + tid];
            s.mp1[tid] = g_mup[gp * LL + tid];
        }
        __syncthreads();

        // E = Sigs - Sp ; dvec = mus - mp1 ; M = A @ Sf
        for (int o = tid; o < LL * LL; o += NT)
            s.E[o] = s.Sigs[o] - s.Sp[(o >> 6) * 65 + (o & 63)];
        if (tid < LL) s.dvec[tid] = s.mus[tid] - s.mp1[tid];
        {
            float acc[8] = {0.f, 0.f, 0.f, 0.f, 0.f, 0.f, 0.f, 0.f};
            for (int l = 0; l < LL; l++) fma8(acc, s.AtT[l * 68 + ti], &s.Sf[l * LL + tj0]);
            store8(&s.M[ti * LL + tj0], acc);
        }
        __syncthreads();

        // GJ: [Sp | M] -> M becomes J^T = Sp^{-1} A Sf  (Sp SPD, no pivoting)
        for (int p = 0; p < LL; p++) {
            if (tid < LL) s.F[tid] = s.Sp[tid * 65 + p];
            __syncthreads();
            if (tid < 128) {
                float inv = 1.f / s.F[p];
                if (tid < 64) s.Sp[p * 65 + tid] *= inv;
                else s.M[p * LL + tid - 64] *= inv;
            }
            __syncthreads();
            for (int idx = tid; idx < 64 * 128; idx += NT) {
                int rr = idx >> 7, c = idx & 127;
                if (rr != p) {
                    float f = s.F[rr];
                    if (c < 64) s.Sp[rr * 65 + c] = fmaf(-f, s.Sp[p * 65 + c], s.Sp[rr * 65 + c]);
                    else {
                        int cc = c - 64;
                        s.M[rr * LL + cc] = fmaf(-f, s.M[p * LL + cc], s.M[rr * LL + cc]);
                    }
                }
            }
            __syncthreads();
        }

        // T1 = J @ E ; mu_s = mf + J dvec
        {
            float acc[8] = {0.f, 0.f, 0.f, 0.f, 0.f, 0.f, 0.f, 0.f};
            for (int j = 0; j < LL; j++) fma8(acc, s.M[j * LL + ti], &s.E[j * LL + tj0]);
            store8(&s.T1[ti * LL + tj0], acc);
        }
        if (tid < LL) {
            float a = s.mf[tid];
            for (int j = 0; j < LL; j++) a = fmaf(s.M[j * LL + tid], s.dvec[j], a);
            s.mus[tid] = a;
            outMu[gf * LL + tid] = a;
        }
        __syncthreads();

        // Sig_s = Sf + T1 @ J^T ; write out + update carry
        {
            float acc[8];
            float4 f0 = *(float4*)&s.Sf[ti * LL + tj0];
            float4 f1 = *(float4*)&s.Sf[ti * LL + tj0 + 4];
            acc[0] = f0.x; acc[1] = f0.y; acc[2] = f0.z; acc[3] = f0.w;
            acc[4] = f1.x; acc[5] = f1.y; acc[6] = f1.z; acc[7] = f1.w;
            for (int k = 0; k < LL; k++) fma8(acc, s.T1[ti * LL + k], &s.M[k * LL + tj0]);
            store8(&s.Sigs[ti * LL + tj0], acc);
            store8(&outSig[gf * 4096 + ti * LL + tj0], acc);
        }
        __syncthreads();
    }
}

// ---------------- launch ----------------
extern "C" void kernel_launch(void* const* d_in, const int* in_sizes, int n_in,
                              void* d_out, int out_size) {
    const float* obs   = (const float*)d_in[0];
    const float* start = (const float*)d_in[1];
    const float* W1    = (const float*)d_in[2];
    const float* b1    = (const float*)d_in[3];
    const float* W2    = (const float*)d_in[4];
    const float* b2    = (const float*)d_in[5];
    const float* A     = (const float*)d_in[6];
    const float* C     = (const float*)d_in[7];

    float* out = (float*)d_out;
    float* outMu  = out;                                   // (T,B,L)      409600
    float* outSig = out + 409600;                          // (T,B,L,L)  26214400
    float* outA   = out + 26624000;                        // (B,T,L,L)  26214400
    float* outC   = out + 52838400;                        // (B,T,D,L)  13107200

    cudaFuncSetAttribute(fwd_kernel, cudaFuncAttributeMaxDynamicSharedMemorySize, (int)sizeof(FwdS));
    cudaFuncSetAttribute(bwd_kernel, cudaFuncAttributeMaxDynamicSharedMemorySize, (int)sizeof(BwdS));

    w_kernel<<<BB * TT, 64>>>(obs, start, W1, b1, W2, b2);

    dim3 gA(4096 / 512, BB * TT / 32);
    mix_kernel<<<gA, 256>>>(A, outA, 4096);
    dim3 gC(2048 / 512, BB * TT / 32);
    mix_kernel<<<gC, 256>>>(C, outC, 2048);

    fwd_kernel<<<BB, NT, sizeof(FwdS)>>>(obs, outA, outC);
    bwd_kernel<<<BB, NT, sizeof(BwdS)>>>(outA, outMu, outSig);
}

// round 2
// speedup vs baseline: 1.8906x; 1.8906x over previous
#include <cuda_runtime.h>

#define BB 64
#define TT 100
#define DD 32
#define LL 64
#define KK 16
#define HH 50
#define NT 512

// ---------------- global scratch (no allocation allowed) ----------------
__device__ float g_w[BB * TT * KK];
__device__ float g_muf[BB * TT * LL];
__device__ float g_mup[BB * TT * LL];
__device__ float g_Sigf[(size_t)BB * TT * LL * LL];
__device__ float g_Sigp[(size_t)BB * TT * LL * LL];
__device__ float g_J[(size_t)BB * (TT - 1) * LL * LL];   // J^T per (t,b)

// ---------------- helpers ----------------
__device__ __forceinline__ void fma8(float acc[8], float a, const float* p) {
    float4 v0 = *(const float4*)p;
    float4 v1 = *(const float4*)(p + 4);
    acc[0] = fmaf(a, v0.x, acc[0]);
    acc[1] = fmaf(a, v0.y, acc[1]);
    acc[2] = fmaf(a, v0.z, acc[2]);
    acc[3] = fmaf(a, v0.w, acc[3]);
    acc[4] = fmaf(a, v1.x, acc[4]);
    acc[5] = fmaf(a, v1.y, acc[5]);
    acc[6] = fmaf(a, v1.z, acc[6]);
    acc[7] = fmaf(a, v1.w, acc[7]);
}

__device__ __forceinline__ void store8(float* p, const float acc[8]) {
    *(float4*)p       = make_float4(acc[0], acc[1], acc[2], acc[3]);
    *(float4*)(p + 4) = make_float4(acc[4], acc[5], acc[6], acc[7]);
}

// ---------------- kernel 1: mixing weights w = softmax(MLP(joint)) ----------------
__global__ void w_kernel(const float* __restrict__ obs, const float* __restrict__ start,
                         const float* __restrict__ W1, const float* __restrict__ b1,
                         const float* __restrict__ W2, const float* __restrict__ b2) {
    __shared__ float sj[DD];
    __shared__ float sh[HH];
    __shared__ float se[KK];
    int bt = blockIdx.x;
    int b = bt / TT, t = bt % TT;
    int tid = threadIdx.x;
    if (tid < DD) sj[tid] = (t == 0) ? start[tid] : obs[((size_t)b * TT + t - 1) * DD + tid];
    __syncthreads();
    if (tid < HH) {
        float a = b1[tid];
        for (int d = 0; d < DD; d++) a = fmaf(sj[d], W1[d * HH + tid], a);
        sh[tid] = fmaxf(a, 0.f);
    }
    __syncthreads();
    if (tid < KK) {
        float a = b2[tid];
        for (int j = 0; j < HH; j++) a = fmaf(sh[j], W2[j * KK + tid], a);
        se[tid] = a;
    }
    __syncthreads();
    if (tid == 0) {
        float m = se[0];
        for (int k = 1; k < KK; k++) m = fmaxf(m, se[k]);
        float ex[KK];
        float ssum = 0.f;
        for (int k = 0; k < KK; k++) { ex[k] = expf(se[k] - m); ssum += ex[k]; }
        float inv = 1.f / ssum;
        for (int k = 0; k < KK; k++) g_w[bt * KK + k] = ex[k] * inv;
    }
}

// ---------------- kernel 2: A_t / C_t mixing ----------------
__global__ void mix_kernel(const float* __restrict__ M, float* __restrict__ out, int ncols) {
    __shared__ float sM[KK * 512];
    __shared__ float sw[32 * KK];
    int tid = threadIdx.x;
    int ij0 = blockIdx.x * 512;
    int bt0 = blockIdx.y * 32;
    for (int idx = tid * 4; idx < KK * 512; idx += 256 * 4) {
        int k = idx / 512, c = idx % 512;
        *(float4*)&sM[idx] = *(const float4*)&M[(size_t)k * ncols + ij0 + c];
    }
    sw[tid]       = g_w[bt0 * KK + tid];
    sw[tid + 256] = g_w[bt0 * KK + tid + 256];
    __syncthreads();

    int btl = (tid >> 5) * 4;
    int jl  = (tid & 31) * 16;
    float acc[4][16];
#pragma unroll
    for (int u = 0; u < 4; u++)
#pragma unroll
        for (int v = 0; v < 16; v++) acc[u][v] = 0.f;

    for (int k = 0; k < KK; k++) {
        float w0 = sw[(btl + 0) * KK + k];
        float w1 = sw[(btl + 1) * KK + k];
        float w2 = sw[(btl + 2) * KK + k];
        float w3 = sw[(btl + 3) * KK + k];
        float m[16];
#pragma unroll
        for (int v = 0; v < 16; v += 4) *(float4*)&m[v] = *(float4*)&sM[k * 512 + jl + v];
#pragma unroll
        for (int v = 0; v < 16; v++) {
            acc[0][v] = fmaf(w0, m[v], acc[0][v]);
            acc[1][v] = fmaf(w1, m[v], acc[1][v]);
            acc[2][v] = fmaf(w2, m[v], acc[2][v]);
            acc[3][v] = fmaf(w3, m[v], acc[3][v]);
        }
    }
#pragma unroll
    for (int u = 0; u < 4; u++) {
        float* dst = &out[(size_t)(bt0 + btl + u) * ncols + ij0 + jl];
#pragma unroll
        for (int v = 0; v < 16; v += 4)
            *(float4*)&dst[v] = make_float4(acc[u][v], acc[u][v + 1], acc[u][v + 2], acc[u][v + 3]);
    }
}

// ---------------- forward Kalman filter: one CTA per batch ----------------
struct FwdS {
    float Sig[LL * LL];     // carry: predicted covariance (stride 64)
    float AtT[LL * 68];     // A_t transposed
    float Ct[DD * LL];      // C row-major
    float CtT[LL * 33];     // C transposed
    float CS[DD * 68];      // C@Sig -> Kg^T (stride 68)
    float S[DD * 33];       // innovation cov
    float ImT[LL * 68];     // (I - Kg C)^T
    float T1[LL * 68];
    float Sigz[LL * LL];
    float Prow[2][100];     // GJ pivot-row broadcast (96 cols used)
    float Fcol[2][DD];      // GJ pivot-column factors
    float Fd[DD];           // final diagonal
    float mu[LL];
    float muz[LL];
    float r[DD];
    float y[DD];
};

extern __shared__ char smem_raw[];

__global__ __launch_bounds__(NT, 1) void fwd_kernel(const float* __restrict__ obs,
                                                    const float* __restrict__ outA,
                                                    const float* __restrict__ outC) {
    FwdS& s = *(FwdS*)smem_raw;
    int tid = threadIdx.x;
    int b = blockIdx.x;
    for (int o = tid; o < LL * LL; o += NT) s.Sig[o] = ((o >> 6) == (o & 63)) ? 20.f : 0.f;
    if (tid < LL) s.mu[tid] = 0.f;
    __syncthreads();

    int ti = tid >> 3;               // 0..63
    int tj0 = (tid & 7) * 8;         // 0..56
    int sd = tid >> 4;               // 0..31
    int e0 = (tid & 15) * 2;         // 0..30
    // GJ mapping: 384 active threads, row gr (0..31), 12 chunks of 8 cols
    int gr = tid / 12;
    int gq = tid - gr * 12;
    int gc = gq * 8;                 // 0..88 (cols 0..31 = S, 32..95 = RHS)
    bool gjA = (tid < 384);
    bool isRHS = gjA && (gc >= 32);

    float v[8];                       // GJ register row-chunk

    for (int t = 0; t < TT; t++) {
        const float* Ag = outA + (size_t)(b * TT + t) * (LL * LL);
        const float* Cg = outC + (size_t)(b * TT + t) * (DD * LL);
        for (int o = tid * 4; o < LL * LL; o += NT * 4) {
            float4 w = *(const float4*)(Ag + o);
            int i = o >> 6, j = o & 63;
            s.AtT[(j + 0) * 68 + i] = w.x;
            s.AtT[(j + 1) * 68 + i] = w.y;
            s.AtT[(j + 2) * 68 + i] = w.z;
            s.AtT[(j + 3) * 68 + i] = w.w;
        }
        {
            int o = tid * 4;
            if (o < DD * LL) {
                float4 w = *(const float4*)&Cg[o];
                *(float4*)&s.Ct[o] = w;
                int i = o >> 6, j = o & 63;
                s.CtT[(j + 0) * 33 + i] = w.x;
                s.CtT[(j + 1) * 33 + i] = w.y;
                s.CtT[(j + 2) * 33 + i] = w.z;
                s.CtT[(j + 3) * 33 + i] = w.w;
            }
        }
        if (tid < DD) s.y[tid] = obs[((size_t)b * TT + t) * DD + tid];
        __syncthreads();

        // phase 2: RHS GJ regs = C@Sig rows (also mirrored into s.CS); r = y - C mu
        if (isRHS) {
#pragma unroll
            for (int i = 0; i < 8; i++) v[i] = 0.f;
            for (int l = 0; l < LL; l++) fma8(v, s.CtT[l * 33 + gr], &s.Sig[l * LL + (gc - 32)]);
            store8(&s.CS[gr * 68 + (gc - 32)], v);
        } else if (tid >= 384 && tid < 384 + DD) {
            int m = tid - 384;
            float a = s.y[m];
            for (int l = 0; l < LL; l++) a = fmaf(-s.CtT[l * 33 + m], s.mu[l], a);
            s.r[m] = a;
        }
        __syncthreads();

        // phase 3: S = CS@C^T + 0.3 I (all threads)
        {
            float a0 = (sd == e0) ? 0.3f : 0.f;
            float a1 = (sd == e0 + 1) ? 0.3f : 0.f;
            for (int k = 0; k < LL; k++) {
                float c = s.CS[sd * 68 + k];
                a0 = fmaf(c, s.CtT[k * 33 + e0], a0);
                a1 = fmaf(c, s.CtT[k * 33 + e0 + 1], a1);
            }
            s.S[sd * 33 + e0] = a0;
            s.S[sd * 33 + e0 + 1] = a1;
        }
        __syncthreads();

        // phase 3b: S-chunk threads load regs; initial publishes for pivot 0
        if (gjA && gc < 32) {
#pragma unroll
            for (int i = 0; i < 8; i++) v[i] = s.S[gr * 33 + gc + i];
        }
        if (gjA && gr == 0) {
#pragma unroll
            for (int i = 0; i < 8; i++) s.Prow[0][gc + i] = v[i];
        }
        if (gjA && gq == 0) s.Fcol[0][gr] = v[0];
        __syncthreads();

        // Gauss-Jordan, deferred normalization, 1 sync per pivot.
        for (int p = 0; p < DD; p++) {
            int par = p & 1;
            if (gjA) {
                float inv = __frcp_rn(s.Fcol[par][p]);
                float f = s.Fcol[par][gr] * inv;
                if (gr != p) {
#pragma unroll
                    for (int i = 0; i < 8; i++) v[i] = fmaf(-f, s.Prow[par][gc + i], v[i]);
                }
                int np = p + 1;
                if (np < DD) {
                    if (gr == np) {
#pragma unroll
                        for (int i = 0; i < 8; i++) s.Prow[par ^ 1][gc + i] = v[i];
                    }
#pragma unroll
                    for (int i = 0; i < 8; i++)
                        if (np == gc + i) s.Fcol[par ^ 1][gr] = v[i];
                } else {
#pragma unroll
                    for (int i = 0; i < 8; i++)
                        if (gr == gc + i) s.Fd[gr] = v[i];
                }
            }
            __syncthreads();
        }

        // writeout: CS <- Kg^T = RHS / diag
        if (isRHS) {
            float dinv = __frcp_rn(s.Fd[gr]);
            float o8[8];
#pragma unroll
            for (int i = 0; i < 8; i++) o8[i] = v[i] * dinv;
            store8(&s.CS[gr * 68 + (gc - 32)], o8);
        }
        __syncthreads();

        // mu_z = mu + Kg r ; ImT = (I - Kg C)^T
        if (tid < LL) {
            float a = s.mu[tid];
            for (int m = 0; m < DD; m++) a = fmaf(s.CS[m * 68 + tid], s.r[m], a);
            s.muz[tid] = a;
        }
        {
            float acc[8];
#pragma unroll
            for (int u = 0; u < 8; u++) acc[u] = (ti == tj0 + u) ? 1.f : 0.f;
            for (int m = 0; m < DD; m++) fma8(acc, -s.CS[m * 68 + ti], &s.Ct[m * LL + tj0]);
#pragma unroll
            for (int u = 0; u < 8; u++) s.ImT[(tj0 + u) * 68 + ti] = acc[u];
        }
        __syncthreads();

        // T1 = Im @ Sig
        {
            float acc[8] = {0.f, 0.f, 0.f, 0.f, 0.f, 0.f, 0.f, 0.f};
            for (int k = 0; k < LL; k++) fma8(acc, s.ImT[k * 68 + ti], &s.Sig[k * LL + tj0]);
            store8(&s.T1[ti * 68 + tj0], acc);
        }
        __syncthreads();

        // Sigz = T1 @ Im^T + 0.3 Kg Kg^T
        {
            float acc[8] = {0.f, 0.f, 0.f, 0.f, 0.f, 0.f, 0.f, 0.f};
            for (int k = 0; k < LL; k++) fma8(acc, s.T1[ti * 68 + k], &s.ImT[k * 68 + tj0]);
            for (int m = 0; m < DD; m++) fma8(acc, 0.3f * s.CS[m * 68 + ti], &s.CS[m * 68 + tj0]);
            store8(&s.Sigz[ti * LL + tj0], acc);
        }
        __syncthreads();

        // store mu_f/Sig_f, mu_p/Sig_p ; T2 = At @ Sigz into T1
        {
            size_t gb = (size_t)t * BB + b;
            if (tid < LL) {
                g_muf[gb * LL + tid] = s.muz[tid];
                g_mup[gb * LL + tid] = s.mu[tid];
            }
            for (int o = tid * 4; o < LL * LL; o += NT * 4) {
                *(float4*)&g_Sigf[gb * 4096 + o] = *(float4*)&s.Sigz[o];
                *(float4*)&g_Sigp[gb * 4096 + o] = *(float4*)&s.Sig[o];
            }
            float acc[8] = {0.f, 0.f, 0.f, 0.f, 0.f, 0.f, 0.f, 0.f};
            for (int l = 0; l < LL; l++) fma8(acc, s.AtT[l * 68 + ti], &s.Sigz[l * LL + tj0]);
            store8(&s.T1[ti * 68 + tj0], acc);
        }
        __syncthreads();

        // Sig_new = T2 @ At^T + 0.8 I ; mu_new = At mu_z
        {
            float acc[8] = {0.f, 0.f, 0.f, 0.f, 0.f, 0.f, 0.f, 0.f};
            for (int k = 0; k < LL; k++) fma8(acc, s.T1[ti * 68 + k], &s.AtT[k * 68 + tj0]);
#pragma unroll
            for (int u = 0; u < 8; u++)
                if (ti == tj0 + u) acc[u] += 0.8f;
            store8(&s.Sig[ti * LL + tj0], acc);
            if (tid < LL) {
                float a = 0.f;
                for (int k = 0; k < LL; k++) a = fmaf(s.AtT[k * 68 + tid], s.muz[k], a);
                s.mu[tid] = a;
            }
        }
        __syncthreads();
    }
}

// ---------------- J precompute: fully parallel over (b, t) ----------------
// Solves Sp_{t+1} X = A_{t+1} @ Sf_t  ->  X = J^T, stored to g_J.
__global__ __launch_bounds__(NT, 2) void jk_kernel(const float* __restrict__ outA) {
    __shared__ float sA[LL * 68];
    __shared__ float sSf[LL * LL];
    __shared__ float Prow[2][144];
    __shared__ float Fcol[2][LL];
    __shared__ float Fd[LL];

    int tid = threadIdx.x;
    int b = blockIdx.x;
    int t = blockIdx.y;                     // 0..T-2
    size_t gf = (size_t)t * BB + b;
    size_t gp = (size_t)(t + 1) * BB + b;

    int gr = tid >> 3;                      // 0..63
    int gq = tid & 7;
    int gc = gq * 16;                       // 0..112 (cols 0..63 = Sp, 64..127 = RHS)
    bool isRHS = (gc >= 64);

    const float* Ag = outA + ((size_t)b * TT + (t + 1)) * (LL * LL);
    for (int o = tid * 4; o < LL * LL; o += NT * 4) {
        float4 w = *(const float4*)(Ag + o);
        *(float4*)&sA[(o >> 6) * 68 + (o & 63)] = w;
        *(float4*)&sSf[o] = *(const float4*)&g_Sigf[gf * 4096 + o];
    }
    __syncthreads();

    float v[16];
    if (isRHS) {
#pragma unroll
        for (int i = 0; i < 16; i++) v[i] = 0.f;
        for (int l = 0; l < LL; l++) {
            float a = sA[gr * 68 + l];
            fma8(v, a, &sSf[l * LL + (gc - 64)]);
            fma8(v + 8, a, &sSf[l * LL + (gc - 64) + 8]);
        }
    } else {
        const float* sp = &g_Sigp[gp * 4096 + gr * LL + gc];
#pragma unroll
        for (int i = 0; i < 16; i += 4) *(float4*)&v[i] = *(const float4*)&sp[i];
    }
    if (gr == 0) {
#pragma unroll
        for (int i = 0; i < 16; i++) Prow[0][gc + i] = v[i];
    }
    if (gq == 0) Fcol[0][gr] = v[0];
    __syncthreads();

    for (int p = 0; p < LL; p++) {
        int par = p & 1;
        float inv = __frcp_rn(Fcol[par][p]);
        float f = Fcol[par][gr] * inv;
        if (gr != p) {
#pragma unroll
            for (int i = 0; i < 16; i++) v[i] = fmaf(-f, Prow[par][gc + i], v[i]);
        }
        int np = p + 1;
        if (np < LL) {
            if (gr == np) {
#pragma unroll
                for (int i = 0; i < 16; i++) Prow[par ^ 1][gc + i] = v[i];
            }
#pragma unroll
            for (int i = 0; i < 16; i++)
                if (np == gc + i) Fcol[par ^ 1][gr] = v[i];
        } else {
#pragma unroll
            for (int i = 0; i < 16; i++)
                if (gr == gc + i) Fd[gr] = v[i];
        }
        __syncthreads();
    }

    if (isRHS) {
        float dinv = __frcp_rn(Fd[gr]);
        float* dst = &g_J[gf * 4096 + gr * LL + (gc - 64)];
#pragma unroll
        for (int i = 0; i < 16; i += 4)
            *(float4*)&dst[i] = make_float4(v[i] * dinv, v[i + 1] * dinv, v[i + 2] * dinv, v[i + 3] * dinv);
    }
}

// ---------------- backward RTS recursion (light): one CTA per batch ----------------
struct BwdS {
    float Sigs[LL * LL];    // carry: smoothed cov at t+1
    float Jt[LL * 68];      // J^T (stride 68)
    float Sf[LL * LL];
    float Sp[LL * LL];
    float E[LL * LL];
    float T1[LL * 68];
    float mus[LL];
    float musN[LL];
    float mf[LL];
    float mp1[LL];
};

__global__ __launch_bounds__(NT, 1) void bwd_kernel(float* __restrict__ outMu,
                                                    float* __restrict__ outSig) {
    BwdS& s = *(BwdS*)smem_raw;
    int tid = threadIdx.x;
    int b = blockIdx.x;
    int ti = tid >> 3;
    int tj0 = (tid & 7) * 8;

    {
        size_t gb = (size_t)(TT - 1) * BB + b;
        for (int o = tid * 4; o < LL * LL; o += NT * 4) {
            float4 w = *(const float4*)&g_Sigf[gb * 4096 + o];
            *(float4*)&s.Sigs[o] = w;
            *(float4*)&outSig[gb * 4096 + o] = w;
        }
        if (tid < LL) {
            float w = g_muf[gb * LL + tid];
            s.mus[tid] = w;
            outMu[gb * LL + tid] = w;
        }
    }
    __syncthreads();

    for (int t = TT - 2; t >= 0; t--) {
        size_t gf = (size_t)t * BB + b;
        size_t gp = (size_t)(t + 1) * BB + b;
        for (int o = tid * 4; o < LL * LL; o += NT * 4) {
            *(float4*)&s.Jt[(o >> 6) * 68 + (o & 63)] = *(const float4*)&g_J[gf * 4096 + o];
            *(float4*)&s.Sf[o] = *(const float4*)&g_Sigf[gf * 4096 + o];
            *(float4*)&s.Sp[o] = *(const float4*)&g_Sigp[gp * 4096 + o];
        }
        if (tid < LL) s.mf[tid] = g_muf[gf * LL + tid];
        else if (tid < 2 * LL) s.mp1[tid - LL] = g_mup[gp * LL + (tid - LL)];
        __syncthreads();

        // E = Sigs - Sp ; mu_s = mf + J (mus - mp1)
        for (int o = tid * 4; o < LL * LL; o += NT * 4) {
            float4 a = *(float4*)&s.Sigs[o];
            float4 c = *(float4*)&s.Sp[o];
            *(float4*)&s.E[o] = make_float4(a.x - c.x, a.y - c.y, a.z - c.z, a.w - c.w);
        }
        if (tid < LL) {
            float a = s.mf[tid];
            for (int k = 0; k < LL; k++) a = fmaf(s.Jt[k * 68 + tid], s.mus[k] - s.mp1[k], a);
            s.musN[tid] = a;
            outMu[gf * LL + tid] = a;
        }
        __syncthreads();

        // T1 = J @ E
        {
            float acc[8] = {0.f, 0.f, 0.f, 0.f, 0.f, 0.f, 0.f, 0.f};
            for (int k = 0; k < LL; k++) fma8(acc, s.Jt[k * 68 + ti], &s.E[k * LL + tj0]);
            store8(&s.T1[ti * 68 + tj0], acc);
        }
        __syncthreads();

        // Sig_s = Sf + T1 @ J^T
        {
            float acc[8];
            float4 f0 = *(float4*)&s.Sf[ti * LL + tj0];
            float4 f1 = *(float4*)&s.Sf[ti * LL + tj0 + 4];
            acc[0] = f0.x; acc[1] = f0.y; acc[2] = f0.z; acc[3] = f0.w;
            acc[4] = f1.x; acc[5] = f1.y; acc[6] = f1.z; acc[7] = f1.w;
            for (int k = 0; k < LL; k++) fma8(acc, s.T1[ti * 68 + k], &s.Jt[k * 68 + tj0]);
            store8(&s.Sigs[ti * LL + tj0], acc);
            store8(&outSig[gf * 4096 + ti * LL + tj0], acc);
        }
        if (tid < LL) s.mus[tid] = s.musN[tid];
        __syncthreads();
    }
}

// ---------------- launch ----------------
extern "C" void kernel_launch(void* const* d_in, const int* in_sizes, int n_in,
                              void* d_out, int out_size) {
    const float* obs   = (const float*)d_in[0];
    const float* start = (const float*)d_in[1];
    const float* W1    = (const float*)d_in[2];
    const float* b1    = (const float*)d_in[3];
    const float* W2    = (const float*)d_in[4];
    const float* b2    = (const float*)d_in[5];
    const float* A     = (const float*)d_in[6];
    const float* C     = (const float*)d_in[7];

    float* out = (float*)d_out;
    float* outMu  = out;                                   // (T,B,L)      409600
    float* outSig = out + 409600;                          // (T,B,L,L)  26214400
    float* outA   = out + 26624000;                        // (B,T,L,L)  26214400
    float* outC   = out + 52838400;                        // (B,T,D,L)  13107200

    cudaFuncSetAttribute(fwd_kernel, cudaFuncAttributeMaxDynamicSharedMemorySize, (int)sizeof(FwdS));
    cudaFuncSetAttribute(bwd_kernel, cudaFuncAttributeMaxDynamicSharedMemorySize, (int)sizeof(BwdS));

    w_kernel<<<BB * TT, 64>>>(obs, start, W1, b1, W2, b2);

    dim3 gA(4096 / 512, BB * TT / 32);
    mix_kernel<<<gA, 256>>>(A, outA, 4096);
    dim3 gC(2048 / 512, BB * TT / 32);
    mix_kernel<<<gC, 256>>>(C, outC, 2048);

    fwd_kernel<<<BB, NT, sizeof(FwdS)>>>(obs, outA, outC);

    dim3 gJ(BB, TT - 1);
    jk_kernel<<<gJ, NT>>>(outA);

    bwd_kernel<<<BB, NT, sizeof(BwdS)>>>(outMu, outSig);
}

// round 3
// speedup vs baseline: 2.2539x; 1.1921x over previous
#include <cuda_runtime.h>

#define BB 64
#define TT 100
#define DD 32
#define LL 64
#define KK 16
#define HH 50
#define NT 512

// ---------------- global scratch (no allocation allowed) ----------------
__device__ float g_w[BB * TT * KK];
__device__ float g_muf[BB * TT * LL];
__device__ float g_mup[BB * TT * LL];
__device__ float g_Sigf[(size_t)BB * TT * LL * LL];
__device__ float g_Sigp[(size_t)BB * TT * LL * LL];
__device__ float g_J[(size_t)BB * (TT - 1) * LL * LL];    // J^T per (t,b)
__device__ float g_B[(size_t)BB * (TT - 1) * LL * LL];    // B_t = Sf - J Sp J^T
__device__ float g_bv[(size_t)BB * (TT - 1) * LL];        // b_t = mf - J mp1

// ---------------- helpers ----------------
__device__ __forceinline__ void fma8(float acc[8], float a, const float* p) {
    float4 v0 = *(const float4*)p;
    float4 v1 = *(const float4*)(p + 4);
    acc[0] = fmaf(a, v0.x, acc[0]);
    acc[1] = fmaf(a, v0.y, acc[1]);
    acc[2] = fmaf(a, v0.z, acc[2]);
    acc[3] = fmaf(a, v0.w, acc[3]);
    acc[4] = fmaf(a, v1.x, acc[4]);
    acc[5] = fmaf(a, v1.y, acc[5]);
    acc[6] = fmaf(a, v1.z, acc[6]);
    acc[7] = fmaf(a, v1.w, acc[7]);
}

__device__ __forceinline__ void store8(float* p, const float acc[8]) {
    *(float4*)p       = make_float4(acc[0], acc[1], acc[2], acc[3]);
    *(float4*)(p + 4) = make_float4(acc[4], acc[5], acc[6], acc[7]);
}

// ---------------- kernel 1: mixing weights w = softmax(MLP(joint)) ----------------
__global__ void w_kernel(const float* __restrict__ obs, const float* __restrict__ start,
                         const float* __restrict__ W1, const float* __restrict__ b1,
                         const float* __restrict__ W2, const float* __restrict__ b2) {
    __shared__ float sj[DD];
    __shared__ float sh[HH];
    __shared__ float se[KK];
    int bt = blockIdx.x;
    int b = bt / TT, t = bt % TT;
    int tid = threadIdx.x;
    if (tid < DD) sj[tid] = (t == 0) ? start[tid] : obs[((size_t)b * TT + t - 1) * DD + tid];
    __syncthreads();
    if (tid < HH) {
        float a = b1[tid];
        for (int d = 0; d < DD; d++) a = fmaf(sj[d], W1[d * HH + tid], a);
        sh[tid] = fmaxf(a, 0.f);
    }
    __syncthreads();
    if (tid < KK) {
        float a = b2[tid];
        for (int j = 0; j < HH; j++) a = fmaf(sh[j], W2[j * KK + tid], a);
        se[tid] = a;
    }
    __syncthreads();
    if (tid == 0) {
        float m = se[0];
        for (int k = 1; k < KK; k++) m = fmaxf(m, se[k]);
        float ex[KK];
        float ssum = 0.f;
        for (int k = 0; k < KK; k++) { ex[k] = expf(se[k] - m); ssum += ex[k]; }
        float inv = 1.f / ssum;
        for (int k = 0; k < KK; k++) g_w[bt * KK + k] = ex[k] * inv;
    }
}

// ---------------- kernel 2: A_t / C_t mixing ----------------
__global__ void mix_kernel(const float* __restrict__ M, float* __restrict__ out, int ncols) {
    __shared__ float sM[KK * 512];
    __shared__ float sw[32 * KK];
    int tid = threadIdx.x;
    int ij0 = blockIdx.x * 512;
    int bt0 = blockIdx.y * 32;
    for (int idx = tid * 4; idx < KK * 512; idx += 256 * 4) {
        int k = idx / 512, c = idx % 512;
        *(float4*)&sM[idx] = *(const float4*)&M[(size_t)k * ncols + ij0 + c];
    }
    sw[tid]       = g_w[bt0 * KK + tid];
    sw[tid + 256] = g_w[bt0 * KK + tid + 256];
    __syncthreads();

    int btl = (tid >> 5) * 4;
    int jl  = (tid & 31) * 16;
    float acc[4][16];
#pragma unroll
    for (int u = 0; u < 4; u++)
#pragma unroll
        for (int v = 0; v < 16; v++) acc[u][v] = 0.f;

    for (int k = 0; k < KK; k++) {
        float w0 = sw[(btl + 0) * KK + k];
        float w1 = sw[(btl + 1) * KK + k];
        float w2 = sw[(btl + 2) * KK + k];
        float w3 = sw[(btl + 3) * KK + k];
        float m[16];
#pragma unroll
        for (int v = 0; v < 16; v += 4) *(float4*)&m[v] = *(float4*)&sM[k * 512 + jl + v];
#pragma unroll
        for (int v = 0; v < 16; v++) {
            acc[0][v] = fmaf(w0, m[v], acc[0][v]);
            acc[1][v] = fmaf(w1, m[v], acc[1][v]);
            acc[2][v] = fmaf(w2, m[v], acc[2][v]);
            acc[3][v] = fmaf(w3, m[v], acc[3][v]);
        }
    }
#pragma unroll
    for (int u = 0; u < 4; u++) {
        float* dst = &out[(size_t)(bt0 + btl + u) * ncols + ij0 + jl];
#pragma unroll
        for (int v = 0; v < 16; v += 4)
            *(float4*)&dst[v] = make_float4(acc[u][v], acc[u][v + 1], acc[u][v + 2], acc[u][v + 3]);
    }
}

// ---------------- forward Kalman filter: one CTA per batch ----------------
struct FwdS {
    float Sig[LL * LL];     // carry: predicted covariance (stride 64)
    float AtT[LL * 68];     // A_t transposed
    float Ct[DD * LL];      // C row-major
    float CtT[LL * 33];     // C transposed
    float CS[DD * 68];      // CS0 = C@Sig (preserved)
    float KgT[DD * 68];     // GJ result: Kg^T = S^{-1} C Sig
    float T1[LL * 68];
    float Sigz[LL * LL];
    float Prow[2][100];     // GJ pivot-row broadcast (96 cols used)
    float Fcol[2][DD];      // GJ pivot-column factors
    float Fd[DD];           // final diagonal
    float mu[LL];
    float muz[LL];
    float r[DD];
    float y[DD];
};

extern __shared__ char smem_raw[];

__global__ __launch_bounds__(NT, 1) void fwd_kernel(const float* __restrict__ obs,
                                                    const float* __restrict__ outA,
                                                    const float* __restrict__ outC) {
    FwdS& s = *(FwdS*)smem_raw;
    int tid = threadIdx.x;
    int b = blockIdx.x;
    for (int o = tid; o < LL * LL; o += NT) s.Sig[o] = ((o >> 6) == (o & 63)) ? 20.f : 0.f;
    if (tid < LL) s.mu[tid] = 0.f;
    __syncthreads();

    int ti = tid >> 3;               // 0..63
    int tj0 = (tid & 7) * 8;         // 0..56
    int sd = tid >> 4;               // 0..31
    int e0 = (tid & 15) * 2;         // 0..30
    // GJ mapping: 384 active threads, row gr (0..31), 12 chunks of 8 cols
    int gr = tid / 12;
    int gq = tid - gr * 12;
    int gc = gq * 8;                 // 0..88 (cols 0..31 = S, 32..95 = RHS)
    bool gjA = (tid < 384);
    bool isRHS = gjA && (gc >= 32);

    float v[8];                       // GJ register row-chunk

    for (int t = 0; t < TT; t++) {
        const float* Ag = outA + (size_t)(b * TT + t) * (LL * LL);
        const float* Cg = outC + (size_t)(b * TT + t) * (DD * LL);
        for (int o = tid * 4; o < LL * LL; o += NT * 4) {
            float4 w = *(const float4*)(Ag + o);
            int i = o >> 6, j = o & 63;
            s.AtT[(j + 0) * 68 + i] = w.x;
            s.AtT[(j + 1) * 68 + i] = w.y;
            s.AtT[(j + 2) * 68 + i] = w.z;
            s.AtT[(j + 3) * 68 + i] = w.w;
        }
        {
            int o = tid * 4;
            if (o < DD * LL) {
                float4 w = *(const float4*)&Cg[o];
                *(float4*)&s.Ct[o] = w;
                int i = o >> 6, j = o & 63;
                s.CtT[(j + 0) * 33 + i] = w.x;
                s.CtT[(j + 1) * 33 + i] = w.y;
                s.CtT[(j + 2) * 33 + i] = w.z;
                s.CtT[(j + 3) * 33 + i] = w.w;
            }
        }
        if (tid < DD) s.y[tid] = obs[((size_t)b * TT + t) * DD + tid];
        __syncthreads();

        // phase 2: RHS GJ regs = C@Sig rows (mirrored into s.CS = CS0); r = y - C mu
        if (isRHS) {
#pragma unroll
            for (int i = 0; i < 8; i++) v[i] = 0.f;
            for (int l = 0; l < LL; l++) fma8(v, s.CtT[l * 33 + gr], &s.Sig[l * LL + (gc - 32)]);
            store8(&s.CS[gr * 68 + (gc - 32)], v);
        } else if (tid >= 384 && tid < 384 + DD) {
            int m = tid - 384;
            float a = s.y[m];
            for (int l = 0; l < LL; l++) a = fmaf(-s.CtT[l * 33 + m], s.mu[l], a);
            s.r[m] = a;
        }
        __syncthreads();

        // phase 3: S = CS0@C^T + 0.3 I (all threads, 2 outputs each) -> Prow/Fcol via regs
        {
            float a0 = (sd == e0) ? 0.3f : 0.f;
            float a1 = (sd == e0 + 1) ? 0.3f : 0.f;
            for (int k = 0; k < LL; k++) {
                float c = s.CS[sd * 68 + k];
                a0 = fmaf(c, s.CtT[k * 33 + e0], a0);
                a1 = fmaf(c, s.CtT[k * 33 + e0 + 1], a1);
            }
            // stage into KgT scratch area temporarily (row sd, cols e0..e0+1) -- use Prow path:
            s.T1[sd * 68 + e0] = a0;           // reuse T1 as S staging (32x32 region)
            s.T1[sd * 68 + e0 + 1] = a1;
        }
        __syncthreads();

        // phase 3b: S-chunk threads load regs; initial publishes for pivot 0
        if (gjA && gc < 32) {
#pragma unroll
            for (int i = 0; i < 8; i++) v[i] = s.T1[gr * 68 + gc + i];
        }
        if (gjA && gr == 0) {
#pragma unroll
            for (int i = 0; i < 8; i++) s.Prow[0][gc + i] = v[i];
        }
        if (gjA && gq == 0) s.Fcol[0][gr] = v[0];
        __syncthreads();

        // Gauss-Jordan, deferred normalization, 1 sync per pivot.
        for (int p = 0; p < DD; p++) {
            int par = p & 1;
            if (gjA) {
                float inv = __frcp_rn(s.Fcol[par][p]);
                float f = s.Fcol[par][gr] * inv;
                if (gr != p) {
#pragma unroll
                    for (int i = 0; i < 8; i++) v[i] = fmaf(-f, s.Prow[par][gc + i], v[i]);
                }
                int np = p + 1;
                if (np < DD) {
                    if (gr == np) {
#pragma unroll
                        for (int i = 0; i < 8; i++) s.Prow[par ^ 1][gc + i] = v[i];
                    }
#pragma unroll
                    for (int i = 0; i < 8; i++)
                        if (np == gc + i) s.Fcol[par ^ 1][gr] = v[i];
                } else {
#pragma unroll
                    for (int i = 0; i < 8; i++)
                        if (gr == gc + i) s.Fd[gr] = v[i];
                }
            }
            __syncthreads();
        }

        // writeout: KgT = RHS / diag
        if (isRHS) {
            float dinv = __frcp_rn(s.Fd[gr]);
            float o8[8];
#pragma unroll
            for (int i = 0; i < 8; i++) o8[i] = v[i] * dinv;
            store8(&s.KgT[gr * 68 + (gc - 32)], o8);
        }
        __syncthreads();

        // phase 6: mu_z = mu + Kg r ; Sigz = Sig - Kg @ CS0  (exact non-Joseph form)
        if (tid < LL) {
            float a = s.mu[tid];
            for (int m = 0; m < DD; m++) a = fmaf(s.KgT[m * 68 + tid], s.r[m], a);
            s.muz[tid] = a;
        }
        {
            float acc[8];
            float4 f0 = *(float4*)&s.Sig[ti * LL + tj0];
            float4 f1 = *(float4*)&s.Sig[ti * LL + tj0 + 4];
            acc[0] = f0.x; acc[1] = f0.y; acc[2] = f0.z; acc[3] = f0.w;
            acc[4] = f1.x; acc[5] = f1.y; acc[6] = f1.z; acc[7] = f1.w;
            for (int m = 0; m < DD; m++) fma8(acc, -s.KgT[m * 68 + ti], &s.CS[m * 68 + tj0]);
            store8(&s.Sigz[ti * LL + tj0], acc);
        }
        __syncthreads();

        // phase 7: store mu_f/Sig_f, mu_p/Sig_p ; T2 = At @ Sigz into T1
        {
            size_t gb = (size_t)t * BB + b;
            if (tid < LL) {
                g_muf[gb * LL + tid] = s.muz[tid];
                g_mup[gb * LL + tid] = s.mu[tid];
            }
            for (int o = tid * 4; o < LL * LL; o += NT * 4) {
                *(float4*)&g_Sigf[gb * 4096 + o] = *(float4*)&s.Sigz[o];
                *(float4*)&g_Sigp[gb * 4096 + o] = *(float4*)&s.Sig[o];
            }
            float acc[8] = {0.f, 0.f, 0.f, 0.f, 0.f, 0.f, 0.f, 0.f};
            for (int l = 0; l < LL; l++) fma8(acc, s.AtT[l * 68 + ti], &s.Sigz[l * LL + tj0]);
            store8(&s.T1[ti * 68 + tj0], acc);
        }
        __syncthreads();

        // phase 8: Sig_new = T2 @ At^T + 0.8 I ; mu_new = At mu_z
        {
            float acc[8] = {0.f, 0.f, 0.f, 0.f, 0.f, 0.f, 0.f, 0.f};
            for (int k = 0; k < LL; k++) fma8(acc, s.T1[ti * 68 + k], &s.AtT[k * 68 + tj0]);
#pragma unroll
            for (int u = 0; u < 8; u++)
                if (ti == tj0 + u) acc[u] += 0.8f;
            store8(&s.Sig[ti * LL + tj0], acc);
            if (tid < LL) {
                float a = 0.f;
                for (int k = 0; k < LL; k++) a = fmaf(s.AtT[k * 68 + tid], s.muz[k], a);
                s.mu[tid] = a;
            }
        }
        __syncthreads();
    }
}

// ---------------- J precompute: fully parallel over (b, t) ----------------
// Solves Sp_{t+1} X = A_{t+1} @ Sf_t -> X = J^T (g_J); also B_t = Sf - RHS^T X,
// b_t = mf - J mp1.
__global__ __launch_bounds__(NT, 2) void jk_kernel(const float* __restrict__ outA) {
    __shared__ float sA[LL * 68];       // A_{t+1}, later reused as X = J^T (stride 68)
    __shared__ float sSf[LL * LL];
    __shared__ float sRHS[LL * 68];     // RHS = A @ Sf (stride 68)
    __shared__ float Prow[2][144];
    __shared__ float Fcol[2][LL];
    __shared__ float Fd[LL];
    __shared__ float smf[LL];
    __shared__ float smp[LL];

    int tid = threadIdx.x;
    int b = blockIdx.x;
    int t = blockIdx.y;                     // 0..T-2
    size_t gf = (size_t)t * BB + b;
    size_t gp = (size_t)(t + 1) * BB + b;

    int gr = tid >> 3;                      // 0..63
    int gq = tid & 7;
    int gc = gq * 16;                       // 0..112 (cols 0..63 = Sp, 64..127 = RHS)
    bool isRHS = (gc >= 64);

    const float* Ag = outA + ((size_t)b * TT + (t + 1)) * (LL * LL);
    for (int o = tid * 4; o < LL * LL; o += NT * 4) {
        float4 w = *(const float4*)(Ag + o);
        *(float4*)&sA[(o >> 6) * 68 + (o & 63)] = w;
        *(float4*)&sSf[o] = *(const float4*)&g_Sigf[gf * 4096 + o];
    }
    if (tid < LL) smf[tid] = g_muf[gf * LL + tid];
    else if (tid < 2 * LL) smp[tid - LL] = g_mup[gp * LL + (tid - LL)];
    __syncthreads();

    float v[16];
    if (isRHS) {
#pragma unroll
        for (int i = 0; i < 16; i++) v[i] = 0.f;
        for (int l = 0; l < LL; l++) {
            float a = sA[gr * 68 + l];
            fma8(v, a, &sSf[l * LL + (gc - 64)]);
            fma8(v + 8, a, &sSf[l * LL + (gc - 64) + 8]);
        }
        // mirror RHS into smem (needed for B_t)
#pragma unroll
        for (int i = 0; i < 16; i += 4)
            *(float4*)&sRHS[gr * 68 + (gc - 64) + i] = make_float4(v[i], v[i + 1], v[i + 2], v[i + 3]);
    } else {
        const float* sp = &g_Sigp[gp * 4096 + gr * LL + gc];
#pragma unroll
        for (int i = 0; i < 16; i += 4) *(float4*)&v[i] = *(const float4*)&sp[i];
    }
    if (gr == 0) {
#pragma unroll
        for (int i = 0; i < 16; i++) Prow[0][gc + i] = v[i];
    }
    if (gq == 0) Fcol[0][gr] = v[0];
    __syncthreads();

    for (int p = 0; p < LL; p++) {
        int par = p & 1;
        float inv = __frcp_rn(Fcol[par][p]);
        float f = Fcol[par][gr] * inv;
        if (gr != p) {
#pragma unroll
            for (int i = 0; i < 16; i++) v[i] = fmaf(-f, Prow[par][gc + i], v[i]);
        }
        int np = p + 1;
        if (np < LL) {
            if (gr == np) {
#pragma unroll
                for (int i = 0; i < 16; i++) Prow[par ^ 1][gc + i] = v[i];
            }
#pragma unroll
            for (int i = 0; i < 16; i++)
                if (np == gc + i) Fcol[par ^ 1][gr] = v[i];
        } else {
#pragma unroll
            for (int i = 0; i < 16; i++)
                if (gr == gc + i) Fd[gr] = v[i];
        }
        __syncthreads();
    }

    // X = J^T: write to g_J and into sA (A no longer needed)
    if (isRHS) {
        float dinv = __frcp_rn(Fd[gr]);
        float* dst = &g_J[gf * 4096 + gr * LL + (gc - 64)];
#pragma unroll
        for (int i = 0; i < 16; i += 4) {
            float4 w = make_float4(v[i] * dinv, v[i + 1] * dinv, v[i + 2] * dinv, v[i + 3] * dinv);
            *(float4*)&dst[i] = w;
            *(float4*)&sA[gr * 68 + (gc - 64) + i] = w;
        }
    }
    __syncthreads();

    // B_t = Sf - RHS^T @ X ; b_t = mf - J mp1
    {
        int ti = tid >> 3;
        int tj0 = (tid & 7) * 8;
        float acc[8];
        float4 f0 = *(float4*)&sSf[ti * LL + tj0];
        float4 f1 = *(float4*)&sSf[ti * LL + tj0 + 4];
        acc[0] = f0.x; acc[1] = f0.y; acc[2] = f0.z; acc[3] = f0.w;
        acc[4] = f1.x; acc[5] = f1.y; acc[6] = f1.z; acc[7] = f1.w;
        for (int m = 0; m < LL; m++) fma8(acc, -sRHS[m * 68 + ti], &sA[m * 68 + tj0]);
        store8(&g_B[gf * 4096 + ti * LL + tj0], acc);
        if (tid < LL) {
            float a = smf[tid];
            for (int m = 0; m < LL; m++) a = fmaf(-sA[m * 68 + tid], smp[m], a);
            g_bv[gf * LL + tid] = a;
        }
    }
}

// ---------------- backward RTS recursion (light): one CTA per batch ----------------
struct BwdS {
    float Sigs[LL * LL];    // carry: smoothed cov at t+1
    float X[LL * 68];       // J^T (stride 68)
    float T1[LL * 68];
    float mus[LL];
    float musN[LL];
    float bv[LL];
};

__global__ __launch_bounds__(NT, 1) void bwd_kernel(float* __restrict__ outMu,
                                                    float* __restrict__ outSig) {
    BwdS& s = *(BwdS*)smem_raw;
    int tid = threadIdx.x;
    int b = blockIdx.x;
    int ti = tid >> 3;
    int tj0 = (tid & 7) * 8;

    {
        size_t gb = (size_t)(TT - 1) * BB + b;
        for (int o = tid * 4; o < LL * LL; o += NT * 4) {
            float4 w = *(const float4*)&g_Sigf[gb * 4096 + o];
            *(float4*)&s.Sigs[o] = w;
            *(float4*)&outSig[gb * 4096 + o] = w;
        }
        if (tid < LL) {
            float w = g_muf[gb * LL + tid];
            s.mus[tid] = w;
            outMu[gb * LL + tid] = w;
        }
    }
    __syncthreads();

    for (int t = TT - 2; t >= 0; t--) {
        size_t gf = (size_t)t * BB + b;
        for (int o = tid * 4; o < LL * LL; o += NT * 4)
            *(float4*)&s.X[(o >> 6) * 68 + (o & 63)] = *(const float4*)&g_J[gf * 4096 + o];
        if (tid < LL) s.bv[tid] = g_bv[gf * LL + tid];
        __syncthreads();

        // T1 = J @ Sigs ; mu_s = b + J mus
        {
            float acc[8] = {0.f, 0.f, 0.f, 0.f, 0.f, 0.f, 0.f, 0.f};
            for (int k = 0; k < LL; k++) fma8(acc, s.X[k * 68 + ti], &s.Sigs[k * LL + tj0]);
            store8(&s.T1[ti * 68 + tj0], acc);
        }
        if (tid < LL) {
            float a = s.bv[tid];
            for (int k = 0; k < LL; k++) a = fmaf(s.X[k * 68 + tid], s.mus[k], a);
            s.musN[tid] = a;
            outMu[gf * LL + tid] = a;
        }
        __syncthreads();

        // Sigs_new = B + T1 @ J^T
        {
            float acc[8];
            const float* Bp = &g_B[gf * 4096 + ti * LL + tj0];
            float4 f0 = *(const float4*)Bp;
            float4 f1 = *(const float4*)(Bp + 4);
            acc[0] = f0.x; acc[1] = f0.y; acc[2] = f0.z; acc[3] = f0.w;
            acc[4] = f1.x; acc[5] = f1.y; acc[6] = f1.z; acc[7] = f1.w;
            for (int k = 0; k < LL; k++) fma8(acc, s.T1[ti * 68 + k], &s.X[k * 68 + tj0]);
            store8(&s.Sigs[ti * LL + tj0], acc);
            store8(&outSig[gf * 4096 + ti * LL + tj0], acc);
        }
        if (tid < LL) s.mus[tid] = s.musN[tid];
        __syncthreads();
    }
}

// ---------------- launch ----------------
extern "C" void kernel_launch(void* const* d_in, const int* in_sizes, int n_in,
                              void* d_out, int out_size) {
    const float* obs   = (const float*)d_in[0];
    const float* start = (const float*)d_in[1];
    const float* W1    = (const float*)d_in[2];
    const float* b1    = (const float*)d_in[3];
    const float* W2    = (const float*)d_in[4];
    const float* b2    = (const float*)d_in[5];
    const float* A     = (const float*)d_in[6];
    const float* C     = (const float*)d_in[7];

    float* out = (float*)d_out;
    float* outMu  = out;                                   // (T,B,L)      409600
    float* outSig = out + 409600;                          // (T,B,L,L)  26214400
    float* outA   = out + 26624000;                        // (B,T,L,L)  26214400
    float* outC   = out + 52838400;                        // (B,T,D,L)  13107200

    cudaFuncSetAttribute(fwd_kernel, cudaFuncAttributeMaxDynamicSharedMemorySize, (int)sizeof(FwdS));
    cudaFuncSetAttribute(bwd_kernel, cudaFuncAttributeMaxDynamicSharedMemorySize, (int)sizeof(BwdS));

    w_kernel<<<BB * TT, 64>>>(obs, start, W1, b1, W2, b2);

    dim3 gA(4096 / 512, BB * TT / 32);
    mix_kernel<<<gA, 256>>>(A, outA, 4096);
    dim3 gC(2048 / 512, BB * TT / 32);
    mix_kernel<<<gC, 256>>>(C, outC, 2048);

    fwd_kernel<<<BB, NT, sizeof(FwdS)>>>(obs, outA, outC);

    dim3 gJ(BB, TT - 1);
    jk_kernel<<<gJ, NT>>>(outA);

    bwd_kernel<<<BB, NT, sizeof(BwdS)>>>(outMu, outSig);
}